// round 1
// baseline (speedup 1.0000x reference)
#include <cuda_runtime.h>
#include <cstdint>

// Problem constants (fixed by the dataset)
#define MAX_NODES 50000
#define DIM 64

// Scratch: z = x @ W, without bias (needed raw for edge gather).
// Static __device__ array per allocation rules.
__device__ float g_z[(size_t)MAX_NODES * DIM];

// ---------------------------------------------------------------------------
// Kernel 1: z = x @ W ; out = z + bias  (out accumulates self-connection term)
// Block = 128 threads, 128 nodes per block. W (16KB) + x tile (32KB) in smem.
// Each thread computes 4 nodes x 16 cols (64 accumulators).
// ---------------------------------------------------------------------------
__global__ void __launch_bounds__(128)
gemm_init_kernel(const float* __restrict__ x,
                 const float* __restrict__ W,
                 const float* __restrict__ bias,
                 float* __restrict__ out,
                 int n)
{
    __shared__ float Ws[64 * 64];     // 16 KB
    __shared__ float Xs[128 * 64];    // 32 KB

    const int tid   = threadIdx.x;
    const int node0 = blockIdx.x * 128;

    // Load W (1024 float4s) coalesced
    {
        const float4* W4  = (const float4*)W;
        float4*       Ws4 = (float4*)Ws;
#pragma unroll
        for (int i = 0; i < 8; i++)
            Ws4[tid + i * 128] = W4[tid + i * 128];
    }
    // Load x tile (128 rows x 16 float4s = 2048 float4s) coalesced, zero-pad tail
    {
        const float4* X4   = (const float4*)x;
        float4*       Xs4v = (float4*)Xs;
#pragma unroll
        for (int i = 0; i < 16; i++) {
            int idx  = tid + i * 128;          // float4 index in tile
            int node = node0 + (idx >> 4);
            float4 v = make_float4(0.f, 0.f, 0.f, 0.f);
            if (node < n) v = X4[(size_t)node * 16 + (idx & 15)];
            Xs4v[idx] = v;
        }
    }
    __syncthreads();

    const int cg = tid & 3;   // column group: cols [cg*16, cg*16+16)
    const int ng = tid >> 2;  // node group: nodes [ng*4, ng*4+4) within tile

    float4 acc[4][4];         // [node][col_quad] -> 64 floats
#pragma unroll
    for (int a = 0; a < 4; a++)
#pragma unroll
        for (int b = 0; b < 4; b++)
            acc[a][b] = make_float4(0.f, 0.f, 0.f, 0.f);

    const float4* WsR = (const float4*)Ws;
    const float4* XsR = (const float4*)Xs;

#pragma unroll
    for (int k4 = 0; k4 < 16; k4++) {
        float4 xv[4];
#pragma unroll
        for (int nl = 0; nl < 4; nl++)
            xv[nl] = XsR[(ng * 4 + nl) * 16 + k4];   // x[node][4k..4k+3]

#pragma unroll
        for (int kk = 0; kk < 4; kk++) {
            const int k = k4 * 4 + kk;
            float4 w0 = WsR[k * 16 + cg * 4 + 0];
            float4 w1 = WsR[k * 16 + cg * 4 + 1];
            float4 w2 = WsR[k * 16 + cg * 4 + 2];
            float4 w3 = WsR[k * 16 + cg * 4 + 3];
#pragma unroll
            for (int nl = 0; nl < 4; nl++) {
                float xk = (kk == 0) ? xv[nl].x :
                           (kk == 1) ? xv[nl].y :
                           (kk == 2) ? xv[nl].z : xv[nl].w;
                acc[nl][0].x += xk * w0.x; acc[nl][0].y += xk * w0.y;
                acc[nl][0].z += xk * w0.z; acc[nl][0].w += xk * w0.w;
                acc[nl][1].x += xk * w1.x; acc[nl][1].y += xk * w1.y;
                acc[nl][1].z += xk * w1.z; acc[nl][1].w += xk * w1.w;
                acc[nl][2].x += xk * w2.x; acc[nl][2].y += xk * w2.y;
                acc[nl][2].z += xk * w2.z; acc[nl][2].w += xk * w2.w;
                acc[nl][3].x += xk * w3.x; acc[nl][3].y += xk * w3.y;
                acc[nl][3].z += xk * w3.z; acc[nl][3].w += xk * w3.w;
            }
        }
    }

    // bias for my 16 columns
    float4 bv[4];
    {
        const float4* B4 = (const float4*)bias;
#pragma unroll
        for (int j = 0; j < 4; j++) bv[j] = B4[cg * 4 + j];
    }

#pragma unroll
    for (int nl = 0; nl < 4; nl++) {
        int node = node0 + ng * 4 + nl;
        if (node >= n) continue;
        float4* zrow = (float4*)(g_z + (size_t)node * 64);
        float4* orow = (float4*)(out + (size_t)node * 64);
#pragma unroll
        for (int j = 0; j < 4; j++) {
            float4 z = acc[nl][j];
            zrow[cg * 4 + j] = z;
            float4 o = make_float4(z.x + bv[j].x, z.y + bv[j].y,
                                   z.z + bv[j].z, z.w + bv[j].w);
            orow[cg * 4 + j] = o;
        }
    }
}

// ---------------------------------------------------------------------------
// Kernel 2: edge scatter. out[dst] += z[src]  via vector RED at L2.
// 16 threads per edge, each does one float4 gather + one red.global.add.v4.f32.
// ---------------------------------------------------------------------------
__global__ void __launch_bounds__(256)
edge_scatter_kernel(const int* __restrict__ src,
                    const int* __restrict__ dst,
                    float* __restrict__ out,
                    int E)
{
    const int64_t t = (int64_t)blockIdx.x * blockDim.x + threadIdx.x;
    const int e = (int)(t >> 4);
    if (e >= E) return;
    const int c = (int)(t & 15) << 2;   // float offset within the 64-dim row

    const int s = __ldg(&src[e]);
    const int d = __ldg(&dst[e]);

    const float4 v = *(const float4*)(g_z + (size_t)s * 64 + c);
    float* p = out + (size_t)d * 64 + c;

    asm volatile("red.global.add.v4.f32 [%0], {%1, %2, %3, %4};"
                 :: "l"(p), "f"(v.x), "f"(v.y), "f"(v.z), "f"(v.w)
                 : "memory");
}

// ---------------------------------------------------------------------------
// Kernel 3: finalize. out = relu(out / degree)
// One thread per float4 (16 per node).
// ---------------------------------------------------------------------------
__global__ void __launch_bounds__(256)
finalize_kernel(const float* __restrict__ deg,
                float* __restrict__ out,
                int n)
{
    const int i = blockIdx.x * blockDim.x + threadIdx.x;   // float4 index
    if (i >= n * 16) return;
    const int node = i >> 4;
    const float invd = 1.0f / __ldg(&deg[node]);

    float4 v = ((float4*)out)[i];
    v.x = fmaxf(v.x * invd, 0.f);
    v.y = fmaxf(v.y * invd, 0.f);
    v.z = fmaxf(v.z * invd, 0.f);
    v.w = fmaxf(v.w * invd, 0.f);
    ((float4*)out)[i] = v;
}

// ---------------------------------------------------------------------------
// Launch. Input order (metadata): x, weight, bias, node_degree, edge_src, edge_dst
// ---------------------------------------------------------------------------
extern "C" void kernel_launch(void* const* d_in, const int* in_sizes, int n_in,
                              void* d_out, int out_size)
{
    const float* x      = (const float*)d_in[0];
    const float* weight = (const float*)d_in[1];
    const float* bias   = (const float*)d_in[2];
    const float* deg    = (const float*)d_in[3];
    const int*   esrc   = (const int*)d_in[4];
    const int*   edst   = (const int*)d_in[5];
    float*       out    = (float*)d_out;

    const int n = in_sizes[0] / DIM;   // 50000
    const int E = in_sizes[4];         // 800000

    // 1) z = x@W ; out = z + bias (self term)
    {
        dim3 grid((n + 127) / 128);
        gemm_init_kernel<<<grid, 128>>>(x, weight, bias, out, n);
    }
    // 2) out[dst] += z[src] over all edges
    {
        int64_t threads = (int64_t)E * 16;
        int blocks = (int)((threads + 255) / 256);
        edge_scatter_kernel<<<blocks, 256>>>(esrc, edst, out, E);
    }
    // 3) out = relu(out / deg)
    {
        int total = n * 16;
        finalize_kernel<<<(total + 255) / 256, 256>>>(deg, out, n);
    }
}